// round 3
// baseline (speedup 1.0000x reference)
#include <cuda_runtime.h>
#include <math.h>

#define B_ 8
#define S_ 1024
#define D_ 1024
#define H_ 16
#define KD 64
#define NEGINF (-1e9f)

// Scratch (allocation-free rule: __device__ globals)
static __device__ float g_q[B_ * S_ * H_ * KD];
static __device__ float g_k[B_ * S_ * H_ * KD];
static __device__ float g_v[B_ * S_ * H_ * KD];
static __device__ float g_ctx[B_ * S_ * H_ * KD];
static __device__ float g_maskf[B_ * S_];

// ---------------------------------------------------------------------------
// Mask dtype sniffing + normalization into g_maskf (1.0 / 0.0 per token).
// The harness widens the reference's bool mask to one of {int32, float32,
// uint8}. Distinguish by byte patterns (values are only 0/1):
//   - any byte >= 2                -> float32 (0x3F800000 bytes)  -> word mode
//   - all bytes at idx%4!=0 zero   -> int32 0/1                   -> word mode
//   - else                         -> 1-byte bool                 -> byte mode
// Single block, deterministic.
// ---------------------------------------------------------------------------
__global__ void mask_norm_kernel(const unsigned char* __restrict__ m)
{
    __shared__ int mode;  // 1 = 4-byte words, 0 = bytes
    if (threadIdx.x == 0) {
        int any_ge2 = 0, any_off = 0;
        for (int i = 0; i < 512; i++) {
            unsigned char v = m[i];
            if (v >= 2) any_ge2 = 1;
            if ((i & 3) && v) any_off = 1;
        }
        mode = (any_ge2 || !any_off) ? 1 : 0;
    }
    __syncthreads();
    const int n = B_ * S_;
    if (mode) {
        const unsigned int* w = (const unsigned int*)m;
        for (int i = threadIdx.x; i < n; i += blockDim.x)
            g_maskf[i] = w[i] ? 1.f : 0.f;
    } else {
        for (int i = threadIdx.x; i < n; i += blockDim.x)
            g_maskf[i] = m[i] ? 1.f : 0.f;
    }
}

// ---------------------------------------------------------------------------
// C[M,N] = A[M,K] @ B[K,N] + bias[N];  M=8192, N=K=1024
// 128x128 block tile, BK=8, 256 threads, 8x8 per-thread micro tile.
// ---------------------------------------------------------------------------
__global__ __launch_bounds__(256, 1)
void gemm_bias_kernel(const float* __restrict__ A,
                      const float* __restrict__ Bm,
                      const float* __restrict__ bias,
                      float* __restrict__ C)
{
    constexpr int N = 1024, Kd = 1024;
    __shared__ float As[8][128];
    __shared__ float Bs[8][128];

    const int tid = threadIdx.x;
    const int ty = tid >> 4, tx = tid & 15;
    const int bm = blockIdx.y, bn = blockIdx.x;

    float acc[8][8];
#pragma unroll
    for (int i = 0; i < 8; i++)
#pragma unroll
        for (int j = 0; j < 8; j++) acc[i][j] = 0.f;

    const int arow = tid >> 1;          // 0..127
    const int acol = (tid & 1) << 2;    // 0 or 4
    const int brow = tid >> 5;          // 0..7
    const int bcol = (tid & 31) << 2;   // 0..124

    const float* Ap = A + (size_t)(bm * 128) * Kd;
    const float* Bp = Bm + bn * 128;

    for (int k0 = 0; k0 < Kd; k0 += 8) {
        float4 a4 = *(const float4*)(Ap + (size_t)arow * Kd + k0 + acol);
        As[acol + 0][arow] = a4.x;
        As[acol + 1][arow] = a4.y;
        As[acol + 2][arow] = a4.z;
        As[acol + 3][arow] = a4.w;
        *(float4*)&Bs[brow][bcol] =
            *(const float4*)(Bp + (size_t)(k0 + brow) * N + bcol);
        __syncthreads();
#pragma unroll
        for (int kk = 0; kk < 8; kk++) {
            float4 a0 = *(const float4*)&As[kk][ty * 8];
            float4 a1 = *(const float4*)&As[kk][ty * 8 + 4];
            float4 b0 = *(const float4*)&Bs[kk][tx * 8];
            float4 b1 = *(const float4*)&Bs[kk][tx * 8 + 4];
            float af[8] = {a0.x, a0.y, a0.z, a0.w, a1.x, a1.y, a1.z, a1.w};
            float bf[8] = {b0.x, b0.y, b0.z, b0.w, b1.x, b1.y, b1.z, b1.w};
#pragma unroll
            for (int i = 0; i < 8; i++)
#pragma unroll
                for (int j = 0; j < 8; j++)
                    acc[i][j] = fmaf(af[i], bf[j], acc[i][j]);
        }
        __syncthreads();
    }

#pragma unroll
    for (int i = 0; i < 8; i++) {
        const int row = bm * 128 + ty * 8 + i;
        const int col = bn * 128 + tx * 8;
        float4 o0, o1;
        o0.x = acc[i][0] + bias[col + 0];
        o0.y = acc[i][1] + bias[col + 1];
        o0.z = acc[i][2] + bias[col + 2];
        o0.w = acc[i][3] + bias[col + 3];
        o1.x = acc[i][4] + bias[col + 4];
        o1.y = acc[i][5] + bias[col + 5];
        o1.z = acc[i][6] + bias[col + 6];
        o1.w = acc[i][7] + bias[col + 7];
        *(float4*)(C + (size_t)row * N + col) = o0;
        *(float4*)(C + (size_t)row * N + col + 4) = o1;
    }
}

// ---------------------------------------------------------------------------
// Flash attention over one (b, h, 128-query tile). Key tiles of 64.
// 256 threads as 16x16; each thread owns 8 rows x 4 cols.
// Replicates reference masking arithmetic exactly:
//   s = raw*0.125f + (1 - mq*mk) * (-1e9f)   in fp32.
// ---------------------------------------------------------------------------
__global__ __launch_bounds__(256, 1)
void attn_kernel()
{
    extern __shared__ float sm[];
    float* Qs  = sm;                 // [128][65]
    float* Ks  = Qs + 128 * 65;      // [64][65]
    float* Vs  = Ks + 64 * 65;       // [64][64]
    float* Ps  = Vs + 64 * 64;       // [128][65]
    float* mqs = Ps + 128 * 65;      // [128]
    float* mks = mqs + 128;          // [64]

    const int tid = threadIdx.x;
    const int ty = tid >> 4, tx = tid & 15;
    const int qt = blockIdx.x;   // 0..7
    const int h  = blockIdx.y;   // 0..15
    const int b  = blockIdx.z;   // 0..7
    const int q0 = qt * 128;

    // Load Q tile [128 x 64]
    for (int t = tid; t < 128 * 16; t += 256) {
        int r = t >> 4, c4 = (t & 15) << 2;
        float4 v4 = *(const float4*)(g_q +
            ((size_t)((b * S_ + q0 + r) * H_ + h)) * KD + c4);
        float* dst = Qs + r * 65 + c4;
        dst[0] = v4.x; dst[1] = v4.y; dst[2] = v4.z; dst[3] = v4.w;
    }
    if (tid < 128) mqs[tid] = g_maskf[b * S_ + q0 + tid];

    float m_i[8], l_i[8], O[8][4];
#pragma unroll
    for (int i = 0; i < 8; i++) {
        m_i[i] = -INFINITY;
        l_i[i] = 0.f;
#pragma unroll
        for (int j = 0; j < 4; j++) O[i][j] = 0.f;
    }

    for (int jt = 0; jt < 16; jt++) {
        const int k0 = jt * 64;
        __syncthreads();  // previous iteration done reading Ks/Vs/Ps
        for (int t = tid; t < 64 * 16; t += 256) {
            int r = t >> 4, c4 = (t & 15) << 2;
            size_t base = ((size_t)((b * S_ + k0 + r) * H_ + h)) * KD + c4;
            float4 kv = *(const float4*)(g_k + base);
            float* kd = Ks + r * 65 + c4;
            kd[0] = kv.x; kd[1] = kv.y; kd[2] = kv.z; kd[3] = kv.w;
            *(float4*)(Vs + r * 64 + c4) = *(const float4*)(g_v + base);
        }
        if (tid < 64) mks[tid] = g_maskf[b * S_ + k0 + tid];
        __syncthreads();

        // Phase 1: scores = Q @ K^T
        float sc[8][4];
#pragma unroll
        for (int i = 0; i < 8; i++)
#pragma unroll
            for (int j = 0; j < 4; j++) sc[i][j] = 0.f;

#pragma unroll 8
        for (int kk = 0; kk < 64; kk++) {
            float af[8], bf[4];
#pragma unroll
            for (int i = 0; i < 8; i++) af[i] = Qs[(ty * 8 + i) * 65 + kk];
#pragma unroll
            for (int j = 0; j < 4; j++) bf[j] = Ks[(tx * 4 + j) * 65 + kk];
#pragma unroll
            for (int i = 0; i < 8; i++)
#pragma unroll
                for (int j = 0; j < 4; j++)
                    sc[i][j] = fmaf(af[i], bf[j], sc[i][j]);
        }

        // Mask + scale + online softmax (row spread across 16 lanes)
#pragma unroll
        for (int i = 0; i < 8; i++) {
            const float mq = mqs[ty * 8 + i];
            float mx = -INFINITY;
#pragma unroll
            for (int j = 0; j < 4; j++) {
                float m2 = mq * mks[tx * 4 + j];
                float s = sc[i][j] * 0.125f + (1.f - m2) * NEGINF;
                sc[i][j] = s;
                mx = fmaxf(mx, s);
            }
#pragma unroll
            for (int off = 8; off; off >>= 1)
                mx = fmaxf(mx, __shfl_xor_sync(0xffffffffu, mx, off));
            const float mn = fmaxf(m_i[i], mx);
            const float corr = __expf(m_i[i] - mn);
            m_i[i] = mn;
            float rs = 0.f;
#pragma unroll
            for (int j = 0; j < 4; j++) {
                float p = __expf(sc[i][j] - mn);
                Ps[(ty * 8 + i) * 65 + tx * 4 + j] = p;
                rs += p;
            }
#pragma unroll
            for (int off = 8; off; off >>= 1)
                rs += __shfl_xor_sync(0xffffffffu, rs, off);
            l_i[i] = l_i[i] * corr + rs;
#pragma unroll
            for (int j = 0; j < 4; j++) O[i][j] *= corr;
        }
        __syncthreads();  // Ps visible to all

        // Phase 2: O += P @ V
#pragma unroll 4
        for (int kk = 0; kk < 64; kk++) {
            float pf[8];
#pragma unroll
            for (int i = 0; i < 8; i++) pf[i] = Ps[(ty * 8 + i) * 65 + kk];
            float4 v4 = *(const float4*)(Vs + kk * 64 + tx * 4);
            float vf[4] = {v4.x, v4.y, v4.z, v4.w};
#pragma unroll
            for (int i = 0; i < 8; i++)
#pragma unroll
                for (int j = 0; j < 4; j++)
                    O[i][j] = fmaf(pf[i], vf[j], O[i][j]);
        }
    }

    // Normalize and write ctx [B,S,H,KD]
#pragma unroll
    for (int i = 0; i < 8; i++) {
        const float inv = 1.f / l_i[i];
        float4 o;
        o.x = O[i][0] * inv;
        o.y = O[i][1] * inv;
        o.z = O[i][2] * inv;
        o.w = O[i][3] * inv;
        *(float4*)(g_ctx +
            ((size_t)((b * S_ + q0 + ty * 8 + i) * H_ + h)) * KD + tx * 4) = o;
    }
}

// ---------------------------------------------------------------------------
extern "C" void kernel_launch(void* const* d_in, const int* in_sizes, int n_in,
                              void* d_out, int out_size)
{
    const float* x  = (const float*)d_in[0];
    const unsigned char* mask = (const unsigned char*)d_in[1];
    const float* Wq = (const float*)d_in[2];
    const float* bq = (const float*)d_in[3];
    const float* Wk = (const float*)d_in[4];
    const float* bk = (const float*)d_in[5];
    const float* Wv = (const float*)d_in[6];
    const float* bv = (const float*)d_in[7];
    const float* Wo = (const float*)d_in[8];
    const float* bo = (const float*)d_in[9];
    float* out = (float*)d_out;

    float *qp, *kp, *vp, *cp;
    cudaGetSymbolAddress((void**)&qp, g_q);
    cudaGetSymbolAddress((void**)&kp, g_k);
    cudaGetSymbolAddress((void**)&vp, g_v);
    cudaGetSymbolAddress((void**)&cp, g_ctx);

    const int smem_bytes =
        (128 * 65 + 64 * 65 + 64 * 64 + 128 * 65 + 128 + 64) * sizeof(float);
    cudaFuncSetAttribute(attn_kernel,
                         cudaFuncAttributeMaxDynamicSharedMemorySize,
                         smem_bytes);

    mask_norm_kernel<<<1, 256>>>(mask);

    dim3 ggrid(8, 64);  // N tiles, M tiles
    gemm_bias_kernel<<<ggrid, 256>>>(x, Wq, bq, qp);
    gemm_bias_kernel<<<ggrid, 256>>>(x, Wk, bk, kp);
    gemm_bias_kernel<<<ggrid, 256>>>(x, Wv, bv, vp);

    attn_kernel<<<dim3(8, 16, 8), 256, smem_bytes>>>();

    gemm_bias_kernel<<<ggrid, 256>>>(cp, Wo, bo, out);
}

// round 5
// speedup vs baseline: 1.6876x; 1.6876x over previous
#include <cuda_runtime.h>
#include <math.h>
#include <stdint.h>

#define B_ 8
#define S_ 1024
#define D_ 1024
#define H_ 16
#define KD 64
#define NEGINF (-1e9f)

// Scratch (allocation-free rule: __device__ globals)
static __device__ float g_q[B_ * S_ * H_ * KD];
static __device__ float g_k[B_ * S_ * H_ * KD];
static __device__ float g_v[B_ * S_ * H_ * KD];
static __device__ float g_ctx[B_ * S_ * H_ * KD];
static __device__ float g_maskf[B_ * S_];

// ---------------------------------------------------------------------------
static __device__ __forceinline__ uint32_t f2tf32(float f) {
    uint32_t u;
    asm("cvt.rna.tf32.f32 %0, %1;" : "=r"(u) : "f"(f));
    return u;
}

static __device__ __forceinline__ void mma_tf32(float* d,
                                                const uint32_t* a,
                                                const uint32_t* b) {
    asm volatile(
        "mma.sync.aligned.m16n8k8.row.col.f32.tf32.tf32.f32 "
        "{%0,%1,%2,%3}, {%4,%5,%6,%7}, {%8,%9}, {%0,%1,%2,%3};"
        : "+f"(d[0]), "+f"(d[1]), "+f"(d[2]), "+f"(d[3])
        : "r"(a[0]), "r"(a[1]), "r"(a[2]), "r"(a[3]),
          "r"(b[0]), "r"(b[1]));
}

// ---------------------------------------------------------------------------
// Mask dtype sniffing + normalization into g_maskf (1.0 / 0.0 per token).
// ---------------------------------------------------------------------------
__global__ void mask_norm_kernel(const unsigned char* __restrict__ m)
{
    __shared__ int mode;  // 1 = 4-byte words, 0 = bytes
    if (threadIdx.x == 0) {
        int any_ge2 = 0, any_off = 0;
        for (int i = 0; i < 512; i++) {
            unsigned char v = m[i];
            if (v >= 2) any_ge2 = 1;
            if ((i & 3) && v) any_off = 1;
        }
        mode = (any_ge2 || !any_off) ? 1 : 0;
    }
    __syncthreads();
    const int n = B_ * S_;
    if (mode) {
        const unsigned int* w = (const unsigned int*)m;
        for (int i = threadIdx.x; i < n; i += blockDim.x)
            g_maskf[i] = w[i] ? 1.f : 0.f;
    } else {
        for (int i = threadIdx.x; i < n; i += blockDim.x)
            g_maskf[i] = m[i] ? 1.f : 0.f;
    }
}

// ---------------------------------------------------------------------------
// tf32 mma.sync GEMM: C[M,N] = A[M,K] @ B[K,N] + bias[N]
// M=8192, N=K=1024. CTA 128x128, BK=32, 8 warps x (64x32) warp tiles.
// A kept [m][k]; B transposed into [n][k] during staging. cvt.rna at staging.
// ---------------------------------------------------------------------------
__global__ __launch_bounds__(256, 2)
void gemm_mma_kernel(const float* __restrict__ A,
                     const float* __restrict__ Bm,
                     const float* __restrict__ bias,
                     float* __restrict__ C)
{
    __shared__ float sA[128][36];
    __shared__ float sB[128][36];

    const int tid = threadIdx.x;
    const int wid = tid >> 5, lane = tid & 31;
    const int bm = blockIdx.y, bn = blockIdx.x;

    const int warp_m = (wid & 1) * 64;   // 0 / 64
    const int warp_n = (wid >> 1) * 32;  // 0 / 32 / 64 / 96
    const int gr = lane >> 2;            // 0..7
    const int tc = lane & 3;             // 0..3

    float acc[4][4][4];
#pragma unroll
    for (int mt = 0; mt < 4; mt++)
#pragma unroll
        for (int nt = 0; nt < 4; nt++)
#pragma unroll
            for (int r = 0; r < 4; r++) acc[mt][nt][r] = 0.f;

    const float* Ap = A + (size_t)(bm * 128) * 1024;
    const float* Bp = Bm + bn * 128;

    const int am = tid >> 3;         // 0..31 (A row within pass)
    const int ak = (tid & 7) * 4;    // 0..28
    const int nb = tid & 127;        // B column (n)
    const int kh = (tid >> 7) * 16;  // B k-half

    for (int k0 = 0; k0 < 1024; k0 += 32) {
        // Stage A [128m x 32k], coalesced 128B rows, cvt.rna to tf32
#pragma unroll
        for (int p = 0; p < 4; p++) {
            const int m = p * 32 + am;
            float4 v = *(const float4*)(Ap + (size_t)m * 1024 + k0 + ak);
            uint32_t* dst = (uint32_t*)&sA[m][ak];
            dst[0] = f2tf32(v.x);
            dst[1] = f2tf32(v.y);
            dst[2] = f2tf32(v.z);
            dst[3] = f2tf32(v.w);
        }
        // Stage B transposed -> sB[n][k]; scalar reads coalesced over n
#pragma unroll
        for (int q = 0; q < 4; q++) {
            const int kk = k0 + kh + q * 4;
            uint32_t* dst = (uint32_t*)&sB[nb][kh + q * 4];
            dst[0] = f2tf32(Bp[(size_t)(kk + 0) * 1024 + nb]);
            dst[1] = f2tf32(Bp[(size_t)(kk + 1) * 1024 + nb]);
            dst[2] = f2tf32(Bp[(size_t)(kk + 2) * 1024 + nb]);
            dst[3] = f2tf32(Bp[(size_t)(kk + 3) * 1024 + nb]);
        }
        __syncthreads();

#pragma unroll
        for (int ks = 0; ks < 4; ks++) {
            const int kq = ks * 8;
            uint32_t af[4][4], bf[4][2];
#pragma unroll
            for (int mt = 0; mt < 4; mt++) {
                const int r = warp_m + mt * 16 + gr;
                af[mt][0] = __float_as_uint(sA[r][kq + tc]);
                af[mt][1] = __float_as_uint(sA[r + 8][kq + tc]);
                af[mt][2] = __float_as_uint(sA[r][kq + tc + 4]);
                af[mt][3] = __float_as_uint(sA[r + 8][kq + tc + 4]);
            }
#pragma unroll
            for (int nt = 0; nt < 4; nt++) {
                const int n = warp_n + nt * 8 + gr;
                bf[nt][0] = __float_as_uint(sB[n][kq + tc]);
                bf[nt][1] = __float_as_uint(sB[n][kq + tc + 4]);
            }
#pragma unroll
            for (int mt = 0; mt < 4; mt++)
#pragma unroll
                for (int nt = 0; nt < 4; nt++)
                    mma_tf32(acc[mt][nt], af[mt], bf[nt]);
        }
        __syncthreads();
    }

    // Epilogue: c0:(g,2tc) c1:(g,2tc+1) c2:(g+8,2tc) c3:(g+8,2tc+1)
#pragma unroll
    for (int mt = 0; mt < 4; mt++) {
        const int row0 = bm * 128 + warp_m + mt * 16 + gr;
#pragma unroll
        for (int nt = 0; nt < 4; nt++) {
            const int col = bn * 128 + warp_n + nt * 8 + 2 * tc;
            const float b0 = bias[col], b1 = bias[col + 1];
            float* c0 = C + (size_t)row0 * 1024 + col;
            float* c1 = C + (size_t)(row0 + 8) * 1024 + col;
            c0[0] = acc[mt][nt][0] + b0;
            c0[1] = acc[mt][nt][1] + b1;
            c1[0] = acc[mt][nt][2] + b0;
            c1[1] = acc[mt][nt][3] + b1;
        }
    }
}

// ---------------------------------------------------------------------------
// Flash attention over one (b, h, 128-query tile). Key tiles of 64. (fp32)
// ---------------------------------------------------------------------------
__global__ __launch_bounds__(256, 1)
void attn_kernel()
{
    extern __shared__ float sm[];
    float* Qs  = sm;                 // [128][65]
    float* Ks  = Qs + 128 * 65;      // [64][65]
    float* Vs  = Ks + 64 * 65;       // [64][64]
    float* Ps  = Vs + 64 * 64;       // [128][65]
    float* mqs = Ps + 128 * 65;      // [128]
    float* mks = mqs + 128;          // [64]

    const int tid = threadIdx.x;
    const int ty = tid >> 4, tx = tid & 15;
    const int qt = blockIdx.x;
    const int h  = blockIdx.y;
    const int b  = blockIdx.z;
    const int q0 = qt * 128;

    for (int t = tid; t < 128 * 16; t += 256) {
        int r = t >> 4, c4 = (t & 15) << 2;
        float4 v4 = *(const float4*)(g_q +
            ((size_t)((b * S_ + q0 + r) * H_ + h)) * KD + c4);
        float* dst = Qs + r * 65 + c4;
        dst[0] = v4.x; dst[1] = v4.y; dst[2] = v4.z; dst[3] = v4.w;
    }
    if (tid < 128) mqs[tid] = g_maskf[b * S_ + q0 + tid];

    float m_i[8], l_i[8], O[8][4];
#pragma unroll
    for (int i = 0; i < 8; i++) {
        m_i[i] = -INFINITY;
        l_i[i] = 0.f;
#pragma unroll
        for (int j = 0; j < 4; j++) O[i][j] = 0.f;
    }

    for (int jt = 0; jt < 16; jt++) {
        const int k0 = jt * 64;
        __syncthreads();
        for (int t = tid; t < 64 * 16; t += 256) {
            int r = t >> 4, c4 = (t & 15) << 2;
            size_t base = ((size_t)((b * S_ + k0 + r) * H_ + h)) * KD + c4;
            float4 kv = *(const float4*)(g_k + base);
            float* kd = Ks + r * 65 + c4;
            kd[0] = kv.x; kd[1] = kv.y; kd[2] = kv.z; kd[3] = kv.w;
            *(float4*)(Vs + r * 64 + c4) = *(const float4*)(g_v + base);
        }
        if (tid < 64) mks[tid] = g_maskf[b * S_ + k0 + tid];
        __syncthreads();

        float sc[8][4];
#pragma unroll
        for (int i = 0; i < 8; i++)
#pragma unroll
            for (int j = 0; j < 4; j++) sc[i][j] = 0.f;

#pragma unroll 8
        for (int kk = 0; kk < 64; kk++) {
            float af[8], bf[4];
#pragma unroll
            for (int i = 0; i < 8; i++) af[i] = Qs[(ty * 8 + i) * 65 + kk];
#pragma unroll
            for (int j = 0; j < 4; j++) bf[j] = Ks[(tx * 4 + j) * 65 + kk];
#pragma unroll
            for (int i = 0; i < 8; i++)
#pragma unroll
                for (int j = 0; j < 4; j++)
                    sc[i][j] = fmaf(af[i], bf[j], sc[i][j]);
        }

#pragma unroll
        for (int i = 0; i < 8; i++) {
            const float mq = mqs[ty * 8 + i];
            float mx = -INFINITY;
#pragma unroll
            for (int j = 0; j < 4; j++) {
                float m2 = mq * mks[tx * 4 + j];
                float s = sc[i][j] * 0.125f + (1.f - m2) * NEGINF;
                sc[i][j] = s;
                mx = fmaxf(mx, s);
            }
#pragma unroll
            for (int off = 8; off; off >>= 1)
                mx = fmaxf(mx, __shfl_xor_sync(0xffffffffu, mx, off));
            const float mn = fmaxf(m_i[i], mx);
            const float corr = __expf(m_i[i] - mn);
            m_i[i] = mn;
            float rs = 0.f;
#pragma unroll
            for (int j = 0; j < 4; j++) {
                float p = __expf(sc[i][j] - mn);
                Ps[(ty * 8 + i) * 65 + tx * 4 + j] = p;
                rs += p;
            }
#pragma unroll
            for (int off = 8; off; off >>= 1)
                rs += __shfl_xor_sync(0xffffffffu, rs, off);
            l_i[i] = l_i[i] * corr + rs;
#pragma unroll
            for (int j = 0; j < 4; j++) O[i][j] *= corr;
        }
        __syncthreads();

#pragma unroll 4
        for (int kk = 0; kk < 64; kk++) {
            float pf[8];
#pragma unroll
            for (int i = 0; i < 8; i++) pf[i] = Ps[(ty * 8 + i) * 65 + kk];
            float4 v4 = *(const float4*)(Vs + kk * 64 + tx * 4);
            float vf[4] = {v4.x, v4.y, v4.z, v4.w};
#pragma unroll
            for (int i = 0; i < 8; i++)
#pragma unroll
                for (int j = 0; j < 4; j++)
                    O[i][j] = fmaf(pf[i], vf[j], O[i][j]);
        }
    }

#pragma unroll
    for (int i = 0; i < 8; i++) {
        const float inv = 1.f / l_i[i];
        float4 o;
        o.x = O[i][0] * inv;
        o.y = O[i][1] * inv;
        o.z = O[i][2] * inv;
        o.w = O[i][3] * inv;
        *(float4*)(g_ctx +
            ((size_t)((b * S_ + q0 + ty * 8 + i) * H_ + h)) * KD + tx * 4) = o;
    }
}

// ---------------------------------------------------------------------------
extern "C" void kernel_launch(void* const* d_in, const int* in_sizes, int n_in,
                              void* d_out, int out_size)
{
    const float* x  = (const float*)d_in[0];
    const unsigned char* mask = (const unsigned char*)d_in[1];
    const float* Wq = (const float*)d_in[2];
    const float* bq = (const float*)d_in[3];
    const float* Wk = (const float*)d_in[4];
    const float* bk = (const float*)d_in[5];
    const float* Wv = (const float*)d_in[6];
    const float* bv = (const float*)d_in[7];
    const float* Wo = (const float*)d_in[8];
    const float* bo = (const float*)d_in[9];
    float* out = (float*)d_out;

    float *qp, *kp, *vp, *cp;
    cudaGetSymbolAddress((void**)&qp, g_q);
    cudaGetSymbolAddress((void**)&kp, g_k);
    cudaGetSymbolAddress((void**)&vp, g_v);
    cudaGetSymbolAddress((void**)&cp, g_ctx);

    const int smem_bytes =
        (128 * 65 + 64 * 65 + 64 * 64 + 128 * 65 + 128 + 64) * sizeof(float);
    cudaFuncSetAttribute(attn_kernel,
                         cudaFuncAttributeMaxDynamicSharedMemorySize,
                         smem_bytes);

    mask_norm_kernel<<<1, 256>>>(mask);

    dim3 ggrid(8, 64);  // N tiles, M tiles
    gemm_mma_kernel<<<ggrid, 256>>>(x, Wq, bq, qp);
    gemm_mma_kernel<<<ggrid, 256>>>(x, Wk, bk, kp);
    gemm_mma_kernel<<<ggrid, 256>>>(x, Wv, bv, vp);

    attn_kernel<<<dim3(8, 16, 8), 256, smem_bytes>>>();

    gemm_mma_kernel<<<ggrid, 256>>>(cp, Wo, bo, out);
}

// round 6
// speedup vs baseline: 1.6959x; 1.0049x over previous
#include <cuda_runtime.h>
#include <math.h>
#include <stdint.h>

#define B_ 8
#define S_ 1024
#define D_ 1024
#define H_ 16
#define KD 64
#define NEGINF (-1e9f)

// Scratch (allocation-free rule: __device__ globals)
static __device__ float g_q[B_ * S_ * H_ * KD];
static __device__ float g_k[B_ * S_ * H_ * KD];
static __device__ float g_v[B_ * S_ * H_ * KD];
static __device__ float g_ctx[B_ * S_ * H_ * KD];
static __device__ float g_maskf[B_ * S_];

// ---------------------------------------------------------------------------
static __device__ __forceinline__ uint32_t f2tf32(float f) {
    uint32_t u;
    asm("cvt.rna.tf32.f32 %0, %1;" : "=r"(u) : "f"(f));
    return u;
}

static __device__ __forceinline__ void mma_tf32(float* d,
                                                const uint32_t* a,
                                                const uint32_t* b) {
    asm volatile(
        "mma.sync.aligned.m16n8k8.row.col.f32.tf32.tf32.f32 "
        "{%0,%1,%2,%3}, {%4,%5,%6,%7}, {%8,%9}, {%0,%1,%2,%3};"
        : "+f"(d[0]), "+f"(d[1]), "+f"(d[2]), "+f"(d[3])
        : "r"(a[0]), "r"(a[1]), "r"(a[2]), "r"(a[3]),
          "r"(b[0]), "r"(b[1]));
}

// ---------------------------------------------------------------------------
// Mask dtype sniffing + normalization into g_maskf (1.0 / 0.0 per token).
// ---------------------------------------------------------------------------
__global__ void mask_norm_kernel(const unsigned char* __restrict__ m)
{
    __shared__ int mode;  // 1 = 4-byte words, 0 = bytes
    if (threadIdx.x == 0) {
        int any_ge2 = 0, any_off = 0;
        for (int i = 0; i < 512; i++) {
            unsigned char v = m[i];
            if (v >= 2) any_ge2 = 1;
            if ((i & 3) && v) any_off = 1;
        }
        mode = (any_ge2 || !any_off) ? 1 : 0;
    }
    __syncthreads();
    const int n = B_ * S_;
    if (mode) {
        const unsigned int* w = (const unsigned int*)m;
        for (int i = threadIdx.x; i < n; i += blockDim.x)
            g_maskf[i] = w[i] ? 1.f : 0.f;
    } else {
        for (int i = threadIdx.x; i < n; i += blockDim.x)
            g_maskf[i] = m[i] ? 1.f : 0.f;
    }
}

// ---------------------------------------------------------------------------
// tf32 mma.sync GEMM: C[M,N] = A[M,K] @ B[K,N] + bias[N]
// M=8192, N=K=1024. CTA 128x128, BK=32, 8 warps x (64x32) warp tiles.
// A kept [m][k]; B transposed into [n][k] during staging. cvt.rna at staging.
// ---------------------------------------------------------------------------
__global__ __launch_bounds__(256, 2)
void gemm_mma_kernel(const float* __restrict__ A,
                     const float* __restrict__ Bm,
                     const float* __restrict__ bias,
                     float* __restrict__ C)
{
    __shared__ float sA[128][36];
    __shared__ float sB[128][36];

    const int tid = threadIdx.x;
    const int wid = tid >> 5, lane = tid & 31;
    const int bm = blockIdx.y, bn = blockIdx.x;

    const int warp_m = (wid & 1) * 64;   // 0 / 64
    const int warp_n = (wid >> 1) * 32;  // 0 / 32 / 64 / 96
    const int gr = lane >> 2;            // 0..7
    const int tc = lane & 3;             // 0..3

    float acc[4][4][4];
#pragma unroll
    for (int mt = 0; mt < 4; mt++)
#pragma unroll
        for (int nt = 0; nt < 4; nt++)
#pragma unroll
            for (int r = 0; r < 4; r++) acc[mt][nt][r] = 0.f;

    const float* Ap = A + (size_t)(bm * 128) * 1024;
    const float* Bp = Bm + bn * 128;

    const int am = tid >> 3;         // 0..31 (A row within pass)
    const int ak = (tid & 7) * 4;    // 0..28
    const int nb = tid & 127;        // B column (n)
    const int kh = (tid >> 7) * 16;  // B k-half

    for (int k0 = 0; k0 < 1024; k0 += 32) {
        // Stage A [128m x 32k], coalesced 128B rows, cvt.rna to tf32
#pragma unroll
        for (int p = 0; p < 4; p++) {
            const int m = p * 32 + am;
            float4 v = *(const float4*)(Ap + (size_t)m * 1024 + k0 + ak);
            uint32_t* dst = (uint32_t*)&sA[m][ak];
            dst[0] = f2tf32(v.x);
            dst[1] = f2tf32(v.y);
            dst[2] = f2tf32(v.z);
            dst[3] = f2tf32(v.w);
        }
        // Stage B transposed -> sB[n][k]; scalar reads coalesced over n
#pragma unroll
        for (int q = 0; q < 4; q++) {
            const int kk = k0 + kh + q * 4;
            uint32_t* dst = (uint32_t*)&sB[nb][kh + q * 4];
            dst[0] = f2tf32(Bp[(size_t)(kk + 0) * 1024 + nb]);
            dst[1] = f2tf32(Bp[(size_t)(kk + 1) * 1024 + nb]);
            dst[2] = f2tf32(Bp[(size_t)(kk + 2) * 1024 + nb]);
            dst[3] = f2tf32(Bp[(size_t)(kk + 3) * 1024 + nb]);
        }
        __syncthreads();

#pragma unroll
        for (int ks = 0; ks < 4; ks++) {
            const int kq = ks * 8;
            uint32_t af[4][4], bf[4][2];
#pragma unroll
            for (int mt = 0; mt < 4; mt++) {
                const int r = warp_m + mt * 16 + gr;
                af[mt][0] = __float_as_uint(sA[r][kq + tc]);
                af[mt][1] = __float_as_uint(sA[r + 8][kq + tc]);
                af[mt][2] = __float_as_uint(sA[r][kq + tc + 4]);
                af[mt][3] = __float_as_uint(sA[r + 8][kq + tc + 4]);
            }
#pragma unroll
            for (int nt = 0; nt < 4; nt++) {
                const int n = warp_n + nt * 8 + gr;
                bf[nt][0] = __float_as_uint(sB[n][kq + tc]);
                bf[nt][1] = __float_as_uint(sB[n][kq + tc + 4]);
            }
#pragma unroll
            for (int mt = 0; mt < 4; mt++)
#pragma unroll
                for (int nt = 0; nt < 4; nt++)
                    mma_tf32(acc[mt][nt], af[mt], bf[nt]);
        }
        __syncthreads();
    }

    // Epilogue: c0:(g,2tc) c1:(g,2tc+1) c2:(g+8,2tc) c3:(g+8,2tc+1)
#pragma unroll
    for (int mt = 0; mt < 4; mt++) {
        const int row0 = bm * 128 + warp_m + mt * 16 + gr;
#pragma unroll
        for (int nt = 0; nt < 4; nt++) {
            const int col = bn * 128 + warp_n + nt * 8 + 2 * tc;
            const float b0 = bias[col], b1 = bias[col + 1];
            float* c0 = C + (size_t)row0 * 1024 + col;
            float* c1 = C + (size_t)(row0 + 8) * 1024 + col;
            c0[0] = acc[mt][nt][0] + b0;
            c0[1] = acc[mt][nt][1] + b1;
            c1[0] = acc[mt][nt][2] + b0;
            c1[1] = acc[mt][nt][3] + b1;
        }
    }
}

// ---------------------------------------------------------------------------
// Flash attention over one (b, h, 128-query tile). Key tiles of 64. (fp32)
// ---------------------------------------------------------------------------
__global__ __launch_bounds__(256, 1)
void attn_kernel()
{
    extern __shared__ float sm[];
    float* Qs  = sm;                 // [128][65]
    float* Ks  = Qs + 128 * 65;      // [64][65]
    float* Vs  = Ks + 64 * 65;       // [64][64]
    float* Ps  = Vs + 64 * 64;       // [128][65]
    float* mqs = Ps + 128 * 65;      // [128]
    float* mks = mqs + 128;          // [64]

    const int tid = threadIdx.x;
    const int ty = tid >> 4, tx = tid & 15;
    const int qt = blockIdx.x;
    const int h  = blockIdx.y;
    const int b  = blockIdx.z;
    const int q0 = qt * 128;

    for (int t = tid; t < 128 * 16; t += 256) {
        int r = t >> 4, c4 = (t & 15) << 2;
        float4 v4 = *(const float4*)(g_q +
            ((size_t)((b * S_ + q0 + r) * H_ + h)) * KD + c4);
        float* dst = Qs + r * 65 + c4;
        dst[0] = v4.x; dst[1] = v4.y; dst[2] = v4.z; dst[3] = v4.w;
    }
    if (tid < 128) mqs[tid] = g_maskf[b * S_ + q0 + tid];

    float m_i[8], l_i[8], O[8][4];
#pragma unroll
    for (int i = 0; i < 8; i++) {
        m_i[i] = -INFINITY;
        l_i[i] = 0.f;
#pragma unroll
        for (int j = 0; j < 4; j++) O[i][j] = 0.f;
    }

    for (int jt = 0; jt < 16; jt++) {
        const int k0 = jt * 64;
        __syncthreads();
        for (int t = tid; t < 64 * 16; t += 256) {
            int r = t >> 4, c4 = (t & 15) << 2;
            size_t base = ((size_t)((b * S_ + k0 + r) * H_ + h)) * KD + c4;
            float4 kv = *(const float4*)(g_k + base);
            float* kd = Ks + r * 65 + c4;
            kd[0] = kv.x; kd[1] = kv.y; kd[2] = kv.z; kd[3] = kv.w;
            *(float4*)(Vs + r * 64 + c4) = *(const float4*)(g_v + base);
        }
        if (tid < 64) mks[tid] = g_maskf[b * S_ + k0 + tid];
        __syncthreads();

        float sc[8][4];
#pragma unroll
        for (int i = 0; i < 8; i++)
#pragma unroll
            for (int j = 0; j < 4; j++) sc[i][j] = 0.f;

#pragma unroll 8
        for (int kk = 0; kk < 64; kk++) {
            float af[8], bf[4];
#pragma unroll
            for (int i = 0; i < 8; i++) af[i] = Qs[(ty * 8 + i) * 65 + kk];
#pragma unroll
            for (int j = 0; j < 4; j++) bf[j] = Ks[(tx * 4 + j) * 65 + kk];
#pragma unroll
            for (int i = 0; i < 8; i++)
#pragma unroll
                for (int j = 0; j < 4; j++)
                    sc[i][j] = fmaf(af[i], bf[j], sc[i][j]);
        }

#pragma unroll
        for (int i = 0; i < 8; i++) {
            const float mq = mqs[ty * 8 + i];
            float mx = -INFINITY;
#pragma unroll
            for (int j = 0; j < 4; j++) {
                float m2 = mq * mks[tx * 4 + j];
                float s = sc[i][j] * 0.125f + (1.f - m2) * NEGINF;
                sc[i][j] = s;
                mx = fmaxf(mx, s);
            }
#pragma unroll
            for (int off = 8; off; off >>= 1)
                mx = fmaxf(mx, __shfl_xor_sync(0xffffffffu, mx, off));
            const float mn = fmaxf(m_i[i], mx);
            const float corr = __expf(m_i[i] - mn);
            m_i[i] = mn;
            float rs = 0.f;
#pragma unroll
            for (int j = 0; j < 4; j++) {
                float p = __expf(sc[i][j] - mn);
                Ps[(ty * 8 + i) * 65 + tx * 4 + j] = p;
                rs += p;
            }
#pragma unroll
            for (int off = 8; off; off >>= 1)
                rs += __shfl_xor_sync(0xffffffffu, rs, off);
            l_i[i] = l_i[i] * corr + rs;
#pragma unroll
            for (int j = 0; j < 4; j++) O[i][j] *= corr;
        }
        __syncthreads();

#pragma unroll 4
        for (int kk = 0; kk < 64; kk++) {
            float pf[8];
#pragma unroll
            for (int i = 0; i < 8; i++) pf[i] = Ps[(ty * 8 + i) * 65 + kk];
            float4 v4 = *(const float4*)(Vs + kk * 64 + tx * 4);
            float vf[4] = {v4.x, v4.y, v4.z, v4.w};
#pragma unroll
            for (int i = 0; i < 8; i++)
#pragma unroll
                for (int j = 0; j < 4; j++)
                    O[i][j] = fmaf(pf[i], vf[j], O[i][j]);
        }
    }

#pragma unroll
    for (int i = 0; i < 8; i++) {
        const float inv = 1.f / l_i[i];
        float4 o;
        o.x = O[i][0] * inv;
        o.y = O[i][1] * inv;
        o.z = O[i][2] * inv;
        o.w = O[i][3] * inv;
        *(float4*)(g_ctx +
            ((size_t)((b * S_ + q0 + ty * 8 + i) * H_ + h)) * KD + tx * 4) = o;
    }
}

// ---------------------------------------------------------------------------
extern "C" void kernel_launch(void* const* d_in, const int* in_sizes, int n_in,
                              void* d_out, int out_size)
{
    const float* x  = (const float*)d_in[0];
    const unsigned char* mask = (const unsigned char*)d_in[1];
    const float* Wq = (const float*)d_in[2];
    const float* bq = (const float*)d_in[3];
    const float* Wk = (const float*)d_in[4];
    const float* bk = (const float*)d_in[5];
    const float* Wv = (const float*)d_in[6];
    const float* bv = (const float*)d_in[7];
    const float* Wo = (const float*)d_in[8];
    const float* bo = (const float*)d_in[9];
    float* out = (float*)d_out;

    float *qp, *kp, *vp, *cp;
    cudaGetSymbolAddress((void**)&qp, g_q);
    cudaGetSymbolAddress((void**)&kp, g_k);
    cudaGetSymbolAddress((void**)&vp, g_v);
    cudaGetSymbolAddress((void**)&cp, g_ctx);

    const int smem_bytes =
        (128 * 65 + 64 * 65 + 64 * 64 + 128 * 65 + 128 + 64) * sizeof(float);
    cudaFuncSetAttribute(attn_kernel,
                         cudaFuncAttributeMaxDynamicSharedMemorySize,
                         smem_bytes);

    mask_norm_kernel<<<1, 256>>>(mask);

    dim3 ggrid(8, 64);  // N tiles, M tiles
    gemm_mma_kernel<<<ggrid, 256>>>(x, Wq, bq, qp);
    gemm_mma_kernel<<<ggrid, 256>>>(x, Wk, bk, kp);
    gemm_mma_kernel<<<ggrid, 256>>>(x, Wv, bv, vp);

    attn_kernel<<<dim3(8, 16, 8), 256, smem_bytes>>>();

    gemm_mma_kernel<<<ggrid, 256>>>(cp, Wo, bo, out);
}